// round 13
// baseline (speedup 1.0000x reference)
#include <cuda_runtime.h>
#include <cuda_fp16.h>
#include <math.h>
#include <stdint.h>

#define NTOK   4096
#define DMODEL 1024
#define DINTER 704
#define NEXP   16
#define NSLOT  (NTOK*2)

// ---------------- device scratch (no allocations allowed) -------------------
__device__ int   g_cnt[NEXP];
__device__ int   g_slot[NEXP][NTOK];
__device__ float g_gate[NEXP][NTOK];

__device__ __align__(16) __half g_x[(size_t)NTOK*DMODEL];
// weights in NATIVE [k][n] layout, fp16: W1/W3 [e][1024][704], W2 [e][704][1024]
__device__ __align__(16) __half g_w1[(size_t)NEXP*DMODEL*DINTER];
__device__ __align__(16) __half g_w3[(size_t)NEXP*DMODEL*DINTER];
__device__ __align__(16) __half g_w2[(size_t)NEXP*DINTER*DMODEL];
__device__ __align__(16) __half g_h[(size_t)NSLOT*DINTER];

// ---------------- PTX helpers ----------------------------------------------
__device__ __forceinline__ uint32_t s2u(const void* p) {
    uint32_t a;
    asm("{ .reg .u64 t; cvta.to.shared.u64 t, %1; cvt.u32.u64 %0, t; }" : "=r"(a) : "l"(p));
    return a;
}
#define SWZ(o) ((o) ^ (((o) >> 3) & 0x70))

__device__ __forceinline__ void cp16(uint32_t dst, const void* src) {
    asm volatile("cp.async.cg.shared.global [%0], [%1], 16;" :: "r"(dst), "l"(src));
}
#define CP_COMMIT() asm volatile("cp.async.commit_group;" ::: "memory")
#define CP_WAIT1()  asm volatile("cp.async.wait_group 1;" ::: "memory")
#define CP_WAIT0()  asm volatile("cp.async.wait_group 0;" ::: "memory")

__device__ __forceinline__ void ldsm4(uint32_t& r0, uint32_t& r1, uint32_t& r2, uint32_t& r3,
                                      uint32_t addr) {
    asm volatile("ldmatrix.sync.aligned.m8n8.x4.shared.b16 {%0,%1,%2,%3}, [%4];"
                 : "=r"(r0), "=r"(r1), "=r"(r2), "=r"(r3) : "r"(addr));
}
__device__ __forceinline__ void ldsm4t(uint32_t& r0, uint32_t& r1, uint32_t& r2, uint32_t& r3,
                                       uint32_t addr) {
    asm volatile("ldmatrix.sync.aligned.m8n8.x4.trans.shared.b16 {%0,%1,%2,%3}, [%4];"
                 : "=r"(r0), "=r"(r1), "=r"(r2), "=r"(r3) : "r"(addr));
}
__device__ __forceinline__ void mma16816(float* d, const uint32_t* a, const uint32_t* b) {
    asm volatile(
        "mma.sync.aligned.m16n8k16.row.col.f32.f16.f16.f32 "
        "{%0,%1,%2,%3},{%4,%5,%6,%7},{%8,%9},{%0,%1,%2,%3};"
        : "+f"(d[0]), "+f"(d[1]), "+f"(d[2]), "+f"(d[3])
        : "r"(a[0]), "r"(a[1]), "r"(a[2]), "r"(a[3]), "r"(b[0]), "r"(b[1]));
}

// ---------------- small kernels ----------------------------------------------
__global__ void k_reset() {
    if (threadIdx.x < NEXP) g_cnt[threadIdx.x] = 0;
}

__global__ void k_router(const float* __restrict__ x, const float* __restrict__ Wg) {
    int n = blockIdx.x;
    const float* xr = x + (size_t)n * DMODEL;
    int tid = threadIdx.x;
    int e = tid >> 3, l = tid & 7;
    const float* wr = Wg + e * DMODEL;
    float s = 0.f;
#pragma unroll 8
    for (int d = l; d < DMODEL; d += 8) s += xr[d] * wr[d];
    s += __shfl_down_sync(0xffffffffu, s, 4);
    s += __shfl_down_sync(0xffffffffu, s, 2);
    s += __shfl_down_sync(0xffffffffu, s, 1);
    __shared__ float logits[NEXP];
    if (l == 0) logits[e] = s;
    __syncthreads();
    if (tid == 0) {
        int i1 = 0; float v1 = logits[0];
#pragma unroll
        for (int j = 1; j < NEXP; j++) if (logits[j] > v1) { v1 = logits[j]; i1 = j; }
        int i2 = -1; float v2 = -3.4e38f;
#pragma unroll
        for (int j = 0; j < NEXP; j++) if (j != i1 && logits[j] > v2) { v2 = logits[j]; i2 = j; }
        float w1 = 1.f / (1.f + expf(v2 - v1));
        float w2 = 1.f - w1;
        int p1 = atomicAdd(&g_cnt[i1], 1);
        g_slot[i1][p1] = n * 2;     g_gate[i1][p1] = w1;
        int p2 = atomicAdd(&g_cnt[i2], 1);
        g_slot[i2][p2] = n * 2 + 1; g_gate[i2][p2] = w2;
    }
}

// fused streaming fp32 -> fp16 conversion: W1 | W3 | W2 | x, 8 elems/thread
#define WGRP ((size_t)NEXP*DMODEL*DINTER/8)   // 1441792
#define XGRP ((size_t)NTOK*DMODEL/8)          // 524288
__global__ void k_cvt_all(const float* __restrict__ x,  const float* __restrict__ W1,
                          const float* __restrict__ W3, const float* __restrict__ W2) {
    size_t gid = (size_t)blockIdx.x * blockDim.x + threadIdx.x;
    const float* src; __half* dst; size_t off;
    if (gid < WGRP)            { src = W1; dst = g_w1; off = gid; }
    else if (gid < 2 * WGRP)   { src = W3; dst = g_w3; off = gid - WGRP; }
    else if (gid < 3 * WGRP)   { src = W2; dst = g_w2; off = gid - 2 * WGRP; }
    else                       { src = x;  dst = g_x;  off = gid - 3 * WGRP;
                                 if (off >= XGRP) return; }
    float4 v0 = ((const float4*)src)[off * 2];
    float4 v1 = ((const float4*)src)[off * 2 + 1];
    __half h[8] = {__float2half(v0.x), __float2half(v0.y), __float2half(v0.z), __float2half(v0.w),
                   __float2half(v1.x), __float2half(v1.y), __float2half(v1.z), __float2half(v1.w)};
    ((uint4*)dst)[off] = *(uint4*)h;
}

// ---------------- GEMM1: H = silu(X W1) * (X W3) -----------------------------
// CTA 128m x 64n, 128 threads (4 warps 2m x 2n), warp 64m x 32n dual-acc.
// k-chunk 64, 3-stage single-sync pipeline.
// Stage: A 16KB (SW128) | B 2 mats x 64 k-rows x 144B (padded) = 34816B
#define G1_BROW  144
#define G1_STAGE (16384 + 2*64*G1_BROW)
#define G1_SMEM  (1024 + 3*G1_STAGE)

__global__ __launch_bounds__(128, 2) void k_gemm1() {
    int e = blockIdx.z;
    int cnt = g_cnt[e];
    int m0 = blockIdx.x * 128;
    if (m0 >= cnt) return;
    int n0 = blockIdx.y * 64;

    extern __shared__ char smem[];
    int* rows = (int*)smem;
    uint32_t sb = s2u(smem);
    int tid = threadIdx.x, lane = tid & 31, wid = tid >> 5;

    {
        int m = m0 + tid;
        rows[tid] = g_slot[e][m < cnt ? m : cnt - 1];
    }
    __syncthreads();

    const __half* w1 = g_w1 + (size_t)e * DMODEL * DINTER;
    const __half* w3 = g_w3 + (size_t)e * DMODEL * DINTER;

    auto load_stage = [&](int it) {
        uint32_t base = sb + 1024 + (it % 3) * G1_STAGE;
        int k0 = it * 64;
#pragma unroll
        for (int q = 0; q < 8; q++) {          // A: 128 rows x 8 chunks, SW128
            int i = tid + q * 128;
            int r = i >> 3, c = i & 7;
            const __half* src = g_x + (size_t)(rows[r] >> 1) * DMODEL + k0 + c * 8;
            cp16(base + SWZ(r * 128 + c * 16), src);
        }
#pragma unroll
        for (int q = 0; q < 8; q++) {          // B: 2 mats x 64 k-rows x 8 chunks, [k][n]
            int i = tid + q * 128;
            int c = i & 7;
            int r = (i >> 3) & 63;
            int mat = i >> 9;
            const __half* src = (mat ? w3 : w1) + (size_t)(k0 + r) * DINTER + n0 + c * 8;
            cp16(base + 16384 + mat * (64 * G1_BROW) + r * G1_BROW + c * 16, src);
        }
        CP_COMMIT();
    };

    float acc1[4][4][4] = {}, acc3[4][4][4] = {};
    int m0w = (wid & 1) * 64, n0w = (wid >> 1) * 32;

    load_stage(0);
    load_stage(1);
    const int ITERS = DMODEL / 64;   // 16
    for (int it = 0; it < ITERS; ++it) {
        if (it + 1 < ITERS) CP_WAIT1(); else CP_WAIT0();
        __syncthreads();
        if (it + 2 < ITERS) load_stage(it + 2);
        uint32_t a = sb + 1024 + (it % 3) * G1_STAGE;
        uint32_t b = a + 16384;
#pragma unroll
        for (int ks = 0; ks < 4; ++ks) {
            uint32_t ah[4][4];
            int colh = ks * 32 + ((lane >> 4) << 4);
#pragma unroll
            for (int i = 0; i < 4; i++) {
                int row = m0w + i * 16 + (lane & 15);
                ldsm4(ah[i][0], ah[i][1], ah[i][2], ah[i][3], a + SWZ(row * 128 + colh));
            }
            // trans B: lane -> k-row, n-col base
            int kl = ks * 16 + ((lane >> 3) & 1) * 8 + (lane & 7);
            int nb = (lane >> 4) * 8;
#pragma unroll
            for (int jj = 0; jj < 2; jj++) {
                int nc = n0w + jj * 16 + nb;
                uint32_t b1[4], b3[4];
                ldsm4t(b1[0], b1[1], b1[2], b1[3], b + kl * G1_BROW + nc * 2);
                ldsm4t(b3[0], b3[1], b3[2], b3[3], b + 64 * G1_BROW + kl * G1_BROW + nc * 2);
#pragma unroll
                for (int i = 0; i < 4; i++) {
                    mma16816(acc1[i][jj * 2 + 0], ah[i], b1 + 0);
                    mma16816(acc1[i][jj * 2 + 1], ah[i], b1 + 2);
                    mma16816(acc3[i][jj * 2 + 0], ah[i], b3 + 0);
                    mma16816(acc3[i][jj * 2 + 1], ah[i], b3 + 2);
                }
            }
        }
    }

    // epilogue: silu(acc1)*acc3, fp16, store H
    int gr = lane >> 2, gc = (lane & 3) * 2;
#pragma unroll
    for (int i = 0; i < 4; i++) {
#pragma unroll
        for (int half = 0; half < 2; half++) {
            int m = m0w + i * 16 + gr + half * 8;
            if (m0 + m < cnt) {
                int slot = rows[m];
                __half* ph = g_h + (size_t)slot * DINTER + n0 + n0w;
#pragma unroll
                for (int j = 0; j < 4; j++) {
                    float a0 = acc1[i][j][half * 2 + 0], a1 = acc1[i][j][half * 2 + 1];
                    float c0 = acc3[i][j][half * 2 + 0], c1 = acc3[i][j][half * 2 + 1];
                    float s0 = a0 / (1.f + __expf(-a0)) * c0;
                    float s1 = a1 / (1.f + __expf(-a1)) * c1;
                    union { __half b[2]; uint32_t u; } uh;
                    uh.b[0] = __float2half(s0);
                    uh.b[1] = __float2half(s1);
                    *(uint32_t*)(ph + j * 8 + gc) = uh.u;
                }
            }
        }
    }
}

// ---------------- GEMM2: out += gate * (H W2) --------------------------------
// CTA 128m x 128n, 128 threads (4 warps 2m x 2n), warp 64m x 64n.
// k-chunk 64, 11 iters, 3-stage. Stage: A 16KB | B 64 k-rows x 272B = 33792B
#define G2_BROW  272
#define G2_STAGE (16384 + 64*G2_BROW)
#define G2_SMEM  (1024 + 3*G2_STAGE)

__global__ __launch_bounds__(128, 2) void k_gemm2(float* __restrict__ out) {
    int e = blockIdx.z;
    int cnt = g_cnt[e];
    int m0 = blockIdx.x * 128;
    if (m0 >= cnt) return;
    int n0 = blockIdx.y * 128;

    extern __shared__ char smem[];
    int*   rows  = (int*)smem;
    float* gates = (float*)(smem + 512);
    uint32_t sb = s2u(smem);
    int tid = threadIdx.x, lane = tid & 31, wid = tid >> 5;

    {
        int m = m0 + tid;
        int mm = m < cnt ? m : cnt - 1;
        rows[tid]  = g_slot[e][mm];
        gates[tid] = g_gate[e][mm];
    }
    __syncthreads();

    const __half* w2 = g_w2 + (size_t)e * DINTER * DMODEL;

    auto load_stage = [&](int it) {
        uint32_t base = sb + 1024 + (it % 3) * G2_STAGE;
        int k0 = it * 64;
#pragma unroll
        for (int q = 0; q < 8; q++) {          // A: 128 gathered H rows, SW128
            int i = tid + q * 128;
            int r = i >> 3, c = i & 7;
            const __half* src = g_h + (size_t)rows[r] * DINTER + k0 + c * 8;
            cp16(base + SWZ(r * 128 + c * 16), src);
        }
#pragma unroll
        for (int q = 0; q < 8; q++) {          // B: 64 k-rows x 16 chunks (128 n), [k][n]
            int i = tid + q * 128;
            int c = i & 15;
            int r = i >> 4;
            const __half* src = w2 + (size_t)(k0 + r) * DMODEL + n0 + c * 8;
            cp16(base + 16384 + r * G2_BROW + c * 16, src);
        }
        CP_COMMIT();
    };

    float acc[4][8][4] = {};
    int m0w = (wid & 1) * 64, n0w = (wid >> 1) * 64;

    load_stage(0);
    load_stage(1);
    const int ITERS = DINTER / 64;   // 11
    for (int it = 0; it < ITERS; ++it) {
        if (it + 1 < ITERS) CP_WAIT1(); else CP_WAIT0();
        __syncthreads();
        if (it + 2 < ITERS) load_stage(it + 2);
        uint32_t a = sb + 1024 + (it % 3) * G2_STAGE;
        uint32_t b = a + 16384;
#pragma unroll
        for (int ks = 0; ks < 4; ++ks) {
            uint32_t ah[4][4];
            int colh = ks * 32 + ((lane >> 4) << 4);
#pragma unroll
            for (int i = 0; i < 4; i++) {
                int row = m0w + i * 16 + (lane & 15);
                ldsm4(ah[i][0], ah[i][1], ah[i][2], ah[i][3], a + SWZ(row * 128 + colh));
            }
            int kl = ks * 16 + ((lane >> 3) & 1) * 8 + (lane & 7);
            int nb = (lane >> 4) * 8;
#pragma unroll
            for (int jj = 0; jj < 4; jj++) {
                int nc = n0w + jj * 16 + nb;
                uint32_t bw[4];
                ldsm4t(bw[0], bw[1], bw[2], bw[3], b + kl * G2_BROW + nc * 2);
#pragma unroll
                for (int i = 0; i < 4; i++) {
                    mma16816(acc[i][jj * 2 + 0], ah[i], bw + 0);
                    mma16816(acc[i][jj * 2 + 1], ah[i], bw + 2);
                }
            }
        }
    }

    int gr = lane >> 2, gc = (lane & 3) * 2;
#pragma unroll
    for (int i = 0; i < 4; i++) {
#pragma unroll
        for (int half = 0; half < 2; half++) {
            int m = m0w + i * 16 + gr + half * 8;
            if (m0 + m < cnt) {
                int tok = rows[m] >> 1;
                float g = gates[m];
                float* op = out + (size_t)tok * DMODEL + n0 + n0w;
#pragma unroll
                for (int j = 0; j < 8; j++) {
                    atomicAdd(op + j * 8 + gc + 0, g * acc[i][j][half * 2 + 0]);
                    atomicAdd(op + j * 8 + gc + 1, g * acc[i][j][half * 2 + 1]);
                }
            }
        }
    }
}

// ---------------------------------------------------------------------------
extern "C" void kernel_launch(void* const* d_in, const int* in_sizes, int n_in,
                              void* d_out, int out_size) {
    const float* x  = (const float*)d_in[0];
    const float* Wg = (const float*)d_in[1];
    const float* W1 = (const float*)d_in[2];
    const float* W2 = (const float*)d_in[3];
    const float* W3 = (const float*)d_in[4];
    float* out = (float*)d_out;

    cudaFuncSetAttribute(k_gemm1, cudaFuncAttributeMaxDynamicSharedMemorySize, G1_SMEM);
    cudaFuncSetAttribute(k_gemm2, cudaFuncAttributeMaxDynamicSharedMemorySize, G2_SMEM);

    cudaMemsetAsync(d_out, 0, (size_t)out_size * sizeof(float), 0);
    k_reset<<<1, 32>>>();
    k_router<<<NTOK, 128>>>(x, Wg);
    int cvt_blocks = (int)((3 * WGRP + XGRP + 255) / 256);
    k_cvt_all<<<cvt_blocks, 256>>>(x, W1, W3, W2);

    k_gemm1<<<dim3(NTOK / 128, DINTER / 64, NEXP), 128, G1_SMEM>>>();
    k_gemm2<<<dim3(NTOK / 128, DMODEL / 128, NEXP), 128, G2_SMEM>>>(out);
}

// round 14
// speedup vs baseline: 1.0121x; 1.0121x over previous
#include <cuda_runtime.h>
#include <cuda_fp16.h>
#include <math.h>
#include <stdint.h>

#define NTOK   4096
#define DMODEL 1024
#define DINTER 704
#define NEXP   16
#define NSLOT  (NTOK*2)

// ---------------- device scratch (no allocations allowed) -------------------
__device__ int   g_cnt[NEXP];
__device__ int   g_slot[NEXP][NTOK];
__device__ float g_gate[NEXP][NTOK];

__device__ __align__(16) __half g_x[(size_t)NTOK*DMODEL];
// weights in NATIVE [k][n] layout, fp16: W1/W3 [e][1024][704], W2 [e][704][1024]
__device__ __align__(16) __half g_w1[(size_t)NEXP*DMODEL*DINTER];
__device__ __align__(16) __half g_w3[(size_t)NEXP*DMODEL*DINTER];
__device__ __align__(16) __half g_w2[(size_t)NEXP*DINTER*DMODEL];
__device__ __align__(16) __half g_h[(size_t)NSLOT*DINTER];

// ---------------- PTX helpers ----------------------------------------------
__device__ __forceinline__ uint32_t s2u(const void* p) {
    uint32_t a;
    asm("{ .reg .u64 t; cvta.to.shared.u64 t, %1; cvt.u32.u64 %0, t; }" : "=r"(a) : "l"(p));
    return a;
}
#define SWZ(o) ((o) ^ (((o) >> 3) & 0x70))

__device__ __forceinline__ void cp16(uint32_t dst, const void* src) {
    asm volatile("cp.async.cg.shared.global [%0], [%1], 16;" :: "r"(dst), "l"(src));
}
#define CP_COMMIT() asm volatile("cp.async.commit_group;" ::: "memory")
#define CP_WAIT1()  asm volatile("cp.async.wait_group 1;" ::: "memory")
#define CP_WAIT0()  asm volatile("cp.async.wait_group 0;" ::: "memory")

__device__ __forceinline__ void ldsm4(uint32_t& r0, uint32_t& r1, uint32_t& r2, uint32_t& r3,
                                      uint32_t addr) {
    asm volatile("ldmatrix.sync.aligned.m8n8.x4.shared.b16 {%0,%1,%2,%3}, [%4];"
                 : "=r"(r0), "=r"(r1), "=r"(r2), "=r"(r3) : "r"(addr));
}
__device__ __forceinline__ void ldsm4t(uint32_t& r0, uint32_t& r1, uint32_t& r2, uint32_t& r3,
                                       uint32_t addr) {
    asm volatile("ldmatrix.sync.aligned.m8n8.x4.trans.shared.b16 {%0,%1,%2,%3}, [%4];"
                 : "=r"(r0), "=r"(r1), "=r"(r2), "=r"(r3) : "r"(addr));
}
__device__ __forceinline__ void mma16816(float* d, const uint32_t* a, const uint32_t* b) {
    asm volatile(
        "mma.sync.aligned.m16n8k16.row.col.f32.f16.f16.f32 "
        "{%0,%1,%2,%3},{%4,%5,%6,%7},{%8,%9},{%0,%1,%2,%3};"
        : "+f"(d[0]), "+f"(d[1]), "+f"(d[2]), "+f"(d[3])
        : "r"(a[0]), "r"(a[1]), "r"(a[2]), "r"(a[3]), "r"(b[0]), "r"(b[1]));
}

// ---------------- small kernels ----------------------------------------------
__global__ void k_reset() {
    if (threadIdx.x < NEXP) g_cnt[threadIdx.x] = 0;
}

__global__ void k_router(const float* __restrict__ x, const float* __restrict__ Wg) {
    int n = blockIdx.x;
    const float* xr = x + (size_t)n * DMODEL;
    int tid = threadIdx.x;
    int e = tid >> 3, l = tid & 7;
    const float* wr = Wg + e * DMODEL;
    float s = 0.f;
#pragma unroll 8
    for (int d = l; d < DMODEL; d += 8) s += xr[d] * wr[d];
    s += __shfl_down_sync(0xffffffffu, s, 4);
    s += __shfl_down_sync(0xffffffffu, s, 2);
    s += __shfl_down_sync(0xffffffffu, s, 1);
    __shared__ float logits[NEXP];
    if (l == 0) logits[e] = s;
    __syncthreads();
    if (tid == 0) {
        int i1 = 0; float v1 = logits[0];
#pragma unroll
        for (int j = 1; j < NEXP; j++) if (logits[j] > v1) { v1 = logits[j]; i1 = j; }
        int i2 = -1; float v2 = -3.4e38f;
#pragma unroll
        for (int j = 0; j < NEXP; j++) if (j != i1 && logits[j] > v2) { v2 = logits[j]; i2 = j; }
        float w1 = 1.f / (1.f + expf(v2 - v1));
        float w2 = 1.f - w1;
        int p1 = atomicAdd(&g_cnt[i1], 1);
        g_slot[i1][p1] = n * 2;     g_gate[i1][p1] = w1;
        int p2 = atomicAdd(&g_cnt[i2], 1);
        g_slot[i2][p2] = n * 2 + 1; g_gate[i2][p2] = w2;
    }
}

// streaming fp32 -> fp16 conversion of W1 | W3 | x (the gemm1 inputs only)
#define WGRP ((size_t)NEXP*DMODEL*DINTER/8)   // 1441792 uint4-groups
#define XGRP ((size_t)NTOK*DMODEL/8)          // 524288
__global__ void k_cvt_pre(const float* __restrict__ x,  const float* __restrict__ W1,
                          const float* __restrict__ W3) {
    size_t gid = (size_t)blockIdx.x * blockDim.x + threadIdx.x;
    const float* src; __half* dst; size_t off;
    if (gid < WGRP)            { src = W1; dst = g_w1; off = gid; }
    else if (gid < 2 * WGRP)   { src = W3; dst = g_w3; off = gid - WGRP; }
    else                       { src = x;  dst = g_x;  off = gid - 2 * WGRP;
                                 if (off >= XGRP) return; }
    float4 v0 = ((const float4*)src)[off * 2];
    float4 v1 = ((const float4*)src)[off * 2 + 1];
    __half h[8] = {__float2half(v0.x), __float2half(v0.y), __float2half(v0.z), __float2half(v0.w),
                   __float2half(v1.x), __float2half(v1.y), __float2half(v1.z), __float2half(v1.w)};
    ((uint4*)dst)[off] = *(uint4*)h;
}

// ---------------- GEMM1: H = silu(X W1) * (X W3) -----------------------------
// CTA 128m x 64n, 256 threads (8 warps 4m x 2n), warp 32m x 32n dual-acc.
// k-chunk 64, 3-stage single-sync pipeline.
// blockIdx.y == DINTER/64 (11): converter CTAs streaming W2 fp32->fp16 (overlap).
// Stage: A 16KB (SW128) | B 2 mats x 64 k-rows x 144B (padded) = 34816B
#define G1_BROW  144
#define G1_STAGE (16384 + 2*64*G1_BROW)
#define G1_SMEM  (1024 + 3*G1_STAGE)
#define NCVT     512   // converter CTAs (32 x-tiles * 16 experts at y==11)

__global__ __launch_bounds__(256, 2) void k_gemm1(const float* __restrict__ W2) {
    // ---- converter slice: overlap W2 conversion with the GEMM CTAs ----
    if (blockIdx.y == DINTER / 64) {
        size_t cid = (size_t)blockIdx.z * 32 + blockIdx.x;      // 0..511
        for (size_t off = cid * 256 + threadIdx.x; off < WGRP; off += (size_t)NCVT * 256) {
            float4 v0 = ((const float4*)W2)[off * 2];
            float4 v1 = ((const float4*)W2)[off * 2 + 1];
            __half h[8] = {__float2half(v0.x), __float2half(v0.y),
                           __float2half(v0.z), __float2half(v0.w),
                           __float2half(v1.x), __float2half(v1.y),
                           __float2half(v1.z), __float2half(v1.w)};
            ((uint4*)g_w2)[off] = *(uint4*)h;
        }
        return;
    }

    int e = blockIdx.z;
    int cnt = g_cnt[e];
    int m0 = blockIdx.x * 128;
    if (m0 >= cnt) return;
    int n0 = blockIdx.y * 64;

    extern __shared__ char smem[];
    int* rows = (int*)smem;
    uint32_t sb = s2u(smem);
    int tid = threadIdx.x, lane = tid & 31, wid = tid >> 5;

    if (tid < 128) {
        int m = m0 + tid;
        rows[tid] = g_slot[e][m < cnt ? m : cnt - 1];
    }
    __syncthreads();

    const __half* w1 = g_w1 + (size_t)e * DMODEL * DINTER;
    const __half* w3 = g_w3 + (size_t)e * DMODEL * DINTER;

    auto load_stage = [&](int it) {
        uint32_t base = sb + 1024 + (it % 3) * G1_STAGE;
        int k0 = it * 64;
#pragma unroll
        for (int q = 0; q < 4; q++) {          // A: 128 rows x 8 chunks, SW128
            int i = tid + q * 256;
            int r = i >> 3, c = i & 7;
            const __half* src = g_x + (size_t)(rows[r] >> 1) * DMODEL + k0 + c * 8;
            cp16(base + SWZ(r * 128 + c * 16), src);
        }
#pragma unroll
        for (int q = 0; q < 4; q++) {          // B: 2 mats x 64 k-rows x 8 chunks, [k][n]
            int i = tid + q * 256;
            int c = i & 7;
            int r = (i >> 3) & 63;
            int mat = i >> 9;
            const __half* src = (mat ? w3 : w1) + (size_t)(k0 + r) * DINTER + n0 + c * 8;
            cp16(base + 16384 + mat * (64 * G1_BROW) + r * G1_BROW + c * 16, src);
        }
        CP_COMMIT();
    };

    float acc1[2][4][4] = {}, acc3[2][4][4] = {};
    int m0w = (wid & 3) * 32, n0w = (wid >> 2) * 32;

    load_stage(0);
    load_stage(1);
    const int ITERS = DMODEL / 64;   // 16
    for (int it = 0; it < ITERS; ++it) {
        if (it + 1 < ITERS) CP_WAIT1(); else CP_WAIT0();
        __syncthreads();
        if (it + 2 < ITERS) load_stage(it + 2);
        uint32_t a = sb + 1024 + (it % 3) * G1_STAGE;
        uint32_t b = a + 16384;
#pragma unroll
        for (int ks = 0; ks < 4; ++ks) {
            uint32_t ah[2][4];
            int colh = ks * 32 + ((lane >> 4) << 4);
#pragma unroll
            for (int i = 0; i < 2; i++) {
                int row = m0w + i * 16 + (lane & 15);
                ldsm4(ah[i][0], ah[i][1], ah[i][2], ah[i][3], a + SWZ(row * 128 + colh));
            }
            // trans B: lane -> k-row, n-col base
            int kl = ks * 16 + ((lane >> 3) & 1) * 8 + (lane & 7);
            int nb = (lane >> 4) * 8;
#pragma unroll
            for (int jj = 0; jj < 2; jj++) {
                int nc = n0w + jj * 16 + nb;
                uint32_t b1[4], b3[4];
                ldsm4t(b1[0], b1[1], b1[2], b1[3], b + kl * G1_BROW + nc * 2);
                ldsm4t(b3[0], b3[1], b3[2], b3[3], b + 64 * G1_BROW + kl * G1_BROW + nc * 2);
#pragma unroll
                for (int i = 0; i < 2; i++) {
                    mma16816(acc1[i][jj * 2 + 0], ah[i], b1 + 0);
                    mma16816(acc1[i][jj * 2 + 1], ah[i], b1 + 2);
                    mma16816(acc3[i][jj * 2 + 0], ah[i], b3 + 0);
                    mma16816(acc3[i][jj * 2 + 1], ah[i], b3 + 2);
                }
            }
        }
    }

    // epilogue: silu(acc1)*acc3, fp16, store H
    int gr = lane >> 2, gc = (lane & 3) * 2;
#pragma unroll
    for (int i = 0; i < 2; i++) {
#pragma unroll
        for (int half = 0; half < 2; half++) {
            int m = m0w + i * 16 + gr + half * 8;
            if (m0 + m < cnt) {
                int slot = rows[m];
                __half* ph = g_h + (size_t)slot * DINTER + n0 + n0w;
#pragma unroll
                for (int j = 0; j < 4; j++) {
                    float a0 = acc1[i][j][half * 2 + 0], a1 = acc1[i][j][half * 2 + 1];
                    float c0 = acc3[i][j][half * 2 + 0], c1 = acc3[i][j][half * 2 + 1];
                    float s0 = a0 / (1.f + __expf(-a0)) * c0;
                    float s1 = a1 / (1.f + __expf(-a1)) * c1;
                    union { __half b[2]; uint32_t u; } uh;
                    uh.b[0] = __float2half(s0);
                    uh.b[1] = __float2half(s1);
                    *(uint32_t*)(ph + j * 8 + gc) = uh.u;
                }
            }
        }
    }
}

// ---------------- GEMM2: out += gate * (H W2) --------------------------------
// CTA 128m x 128n, 256 threads, k-chunk 64, 11 iters, 3-stage. warp = 32m x 64n.
// Stage: A 16KB | B 64 k-rows x 272B (padded) = 33792B
#define G2_BROW  272
#define G2_STAGE (16384 + 64*G2_BROW)
#define G2_SMEM  (1024 + 3*G2_STAGE)

__global__ __launch_bounds__(256, 2) void k_gemm2(float* __restrict__ out) {
    int e = blockIdx.z;
    int cnt = g_cnt[e];
    int m0 = blockIdx.x * 128;
    if (m0 >= cnt) return;
    int n0 = blockIdx.y * 128;

    extern __shared__ char smem[];
    int*   rows  = (int*)smem;
    float* gates = (float*)(smem + 512);
    uint32_t sb = s2u(smem);
    int tid = threadIdx.x, lane = tid & 31, wid = tid >> 5;

    if (tid < 128) {
        int m = m0 + tid;
        int mm = m < cnt ? m : cnt - 1;
        rows[tid]  = g_slot[e][mm];
        gates[tid] = g_gate[e][mm];
    }
    __syncthreads();

    const __half* w2 = g_w2 + (size_t)e * DINTER * DMODEL;

    auto load_stage = [&](int it) {
        uint32_t base = sb + 1024 + (it % 3) * G2_STAGE;
        int k0 = it * 64;
#pragma unroll
        for (int q = 0; q < 4; q++) {          // A: 128 gathered H rows, SW128
            int i = tid + q * 256;
            int r = i >> 3, c = i & 7;
            const __half* src = g_h + (size_t)rows[r] * DINTER + k0 + c * 8;
            cp16(base + SWZ(r * 128 + c * 16), src);
        }
#pragma unroll
        for (int q = 0; q < 4; q++) {          // B: 64 k-rows x 16 chunks (128 n), [k][n]
            int i = tid + q * 256;
            int c = i & 15;
            int r = i >> 4;
            const __half* src = w2 + (size_t)(k0 + r) * DMODEL + n0 + c * 8;
            cp16(base + 16384 + r * G2_BROW + c * 16, src);
        }
        CP_COMMIT();
    };

    float acc[2][8][4] = {};
    int m0w = (wid & 3) * 32, n0w = (wid >> 2) * 64;

    load_stage(0);
    load_stage(1);
    const int ITERS = DINTER / 64;   // 11
    for (int it = 0; it < ITERS; ++it) {
        if (it + 1 < ITERS) CP_WAIT1(); else CP_WAIT0();
        __syncthreads();
        if (it + 2 < ITERS) load_stage(it + 2);
        uint32_t a = sb + 1024 + (it % 3) * G2_STAGE;
        uint32_t b = a + 16384;
#pragma unroll
        for (int ks = 0; ks < 4; ++ks) {
            uint32_t ah[2][4];
            int colh = ks * 32 + ((lane >> 4) << 4);
#pragma unroll
            for (int i = 0; i < 2; i++) {
                int row = m0w + i * 16 + (lane & 15);
                ldsm4(ah[i][0], ah[i][1], ah[i][2], ah[i][3], a + SWZ(row * 128 + colh));
            }
            int kl = ks * 16 + ((lane >> 3) & 1) * 8 + (lane & 7);
            int nb = (lane >> 4) * 8;
#pragma unroll
            for (int jj = 0; jj < 4; jj++) {
                int nc = n0w + jj * 16 + nb;
                uint32_t bw[4];
                ldsm4t(bw[0], bw[1], bw[2], bw[3], b + kl * G2_BROW + nc * 2);
#pragma unroll
                for (int i = 0; i < 2; i++) {
                    mma16816(acc[i][jj * 2 + 0], ah[i], bw + 0);
                    mma16816(acc[i][jj * 2 + 1], ah[i], bw + 2);
                }
            }
        }
    }

    int gr = lane >> 2, gc = (lane & 3) * 2;
#pragma unroll
    for (int i = 0; i < 2; i++) {
#pragma unroll
        for (int half = 0; half < 2; half++) {
            int m = m0w + i * 16 + gr + half * 8;
            if (m0 + m < cnt) {
                int tok = rows[m] >> 1;
                float g = gates[m];
                float* op = out + (size_t)tok * DMODEL + n0 + n0w;
#pragma unroll
                for (int j = 0; j < 8; j++) {
                    atomicAdd(op + j * 8 + gc + 0, g * acc[i][j][half * 2 + 0]);
                    atomicAdd(op + j * 8 + gc + 1, g * acc[i][j][half * 2 + 1]);
                }
            }
        }
    }
}

// ---------------------------------------------------------------------------
extern "C" void kernel_launch(void* const* d_in, const int* in_sizes, int n_in,
                              void* d_out, int out_size) {
    const float* x  = (const float*)d_in[0];
    const float* Wg = (const float*)d_in[1];
    const float* W1 = (const float*)d_in[2];
    const float* W2 = (const float*)d_in[3];
    const float* W3 = (const float*)d_in[4];
    float* out = (float*)d_out;

    cudaFuncSetAttribute(k_gemm1, cudaFuncAttributeMaxDynamicSharedMemorySize, G1_SMEM);
    cudaFuncSetAttribute(k_gemm2, cudaFuncAttributeMaxDynamicSharedMemorySize, G2_SMEM);

    cudaMemsetAsync(d_out, 0, (size_t)out_size * sizeof(float), 0);
    k_reset<<<1, 32>>>();
    k_router<<<NTOK, 128>>>(x, Wg);
    int cvt_blocks = (int)((2 * WGRP + XGRP + 255) / 256);
    k_cvt_pre<<<cvt_blocks, 256>>>(x, W1, W3);

    // grid.y = 12: y 0..10 = GEMM n-tiles, y 11 = W2-converter CTAs (overlap)
    k_gemm1<<<dim3(NTOK / 128, DINTER / 64 + 1, NEXP), 256, G1_SMEM>>>(W2);
    k_gemm2<<<dim3(NTOK / 128, DMODEL / 128, NEXP), 256, G2_SMEM>>>(out);
}

// round 16
// speedup vs baseline: 1.0484x; 1.0359x over previous
#include <cuda_runtime.h>
#include <cuda_fp16.h>
#include <math.h>
#include <stdint.h>

#define NTOK   4096
#define DMODEL 1024
#define DINTER 704
#define NEXP   16
#define NSLOT  (NTOK*2)

// ---------------- device scratch (no allocations allowed) -------------------
__device__ int   g_cnt[NEXP];
__device__ int   g_slot[NEXP][NTOK];
__device__ float g_gate[NEXP][NTOK];

__device__ __align__(16) __half g_x[(size_t)NTOK*DMODEL];
// weights in NATIVE [k][n] layout, fp16: W1/W3 [e][1024][704], W2 [e][704][1024]
__device__ __align__(16) __half g_w1[(size_t)NEXP*DMODEL*DINTER];
__device__ __align__(16) __half g_w3[(size_t)NEXP*DMODEL*DINTER];
__device__ __align__(16) __half g_w2[(size_t)NEXP*DINTER*DMODEL];
__device__ __align__(16) __half g_h[(size_t)NSLOT*DINTER];

// ---------------- PTX helpers ----------------------------------------------
__device__ __forceinline__ uint32_t s2u(const void* p) {
    uint32_t a;
    asm("{ .reg .u64 t; cvta.to.shared.u64 t, %1; cvt.u32.u64 %0, t; }" : "=r"(a) : "l"(p));
    return a;
}
#define SWZ(o) ((o) ^ (((o) >> 3) & 0x70))

__device__ __forceinline__ void cp16(uint32_t dst, const void* src) {
    asm volatile("cp.async.cg.shared.global [%0], [%1], 16;" :: "r"(dst), "l"(src));
}
#define CP_COMMIT() asm volatile("cp.async.commit_group;" ::: "memory")
#define CP_WAIT1()  asm volatile("cp.async.wait_group 1;" ::: "memory")
#define CP_WAIT0()  asm volatile("cp.async.wait_group 0;" ::: "memory")

__device__ __forceinline__ void ldsm4(uint32_t& r0, uint32_t& r1, uint32_t& r2, uint32_t& r3,
                                      uint32_t addr) {
    asm volatile("ldmatrix.sync.aligned.m8n8.x4.shared.b16 {%0,%1,%2,%3}, [%4];"
                 : "=r"(r0), "=r"(r1), "=r"(r2), "=r"(r3) : "r"(addr));
}
__device__ __forceinline__ void ldsm4t(uint32_t& r0, uint32_t& r1, uint32_t& r2, uint32_t& r3,
                                       uint32_t addr) {
    asm volatile("ldmatrix.sync.aligned.m8n8.x4.trans.shared.b16 {%0,%1,%2,%3}, [%4];"
                 : "=r"(r0), "=r"(r1), "=r"(r2), "=r"(r3) : "r"(addr));
}
__device__ __forceinline__ void mma16816(float* d, const uint32_t* a, const uint32_t* b) {
    asm volatile(
        "mma.sync.aligned.m16n8k16.row.col.f32.f16.f16.f32 "
        "{%0,%1,%2,%3},{%4,%5,%6,%7},{%8,%9},{%0,%1,%2,%3};"
        : "+f"(d[0]), "+f"(d[1]), "+f"(d[2]), "+f"(d[3])
        : "r"(a[0]), "r"(a[1]), "r"(a[2]), "r"(a[3]), "r"(b[0]), "r"(b[1]));
}

// ---------------- small kernels ----------------------------------------------
__global__ void k_reset() {
    if (threadIdx.x < NEXP) g_cnt[threadIdx.x] = 0;
}

// ---------------- fused prep: router + x->fp16 + W1/W3->fp16 ------------------
// blocks [0, 256): router, 16 tokens each, Wg cached in smem, x row staged+converted
// blocks [256, 1024): grid-stride streaming conversion of W1 | W3
#define WGRP ((size_t)NEXP*DMODEL*DINTER/8)   // 1441792 uint4-groups per weight
#define PREP_RTR   256
#define PREP_CVT   768
#define TOK_PER_BLK 16
#define PREP_SMEM  (DMODEL*NEXP*4 + DMODEL*4 + 64)   // Wg 64KB + xrow 4KB + logits

__global__ __launch_bounds__(256) void k_prep(const float* __restrict__ x,
                                              const float* __restrict__ Wg,
                                              const float* __restrict__ W1,
                                              const float* __restrict__ W3) {
    int tid = threadIdx.x;
    if (blockIdx.x >= PREP_RTR) {
        // ---- converter: W1 | W3 fp32 -> fp16, streaming ----
        size_t cid = blockIdx.x - PREP_RTR;
        for (size_t off = cid * 256 + tid; off < 2 * WGRP; off += (size_t)PREP_CVT * 256) {
            const float* src; __half* dst; size_t o;
            if (off < WGRP) { src = W1; dst = g_w1; o = off; }
            else            { src = W3; dst = g_w3; o = off - WGRP; }
            float4 v0 = ((const float4*)src)[o * 2];
            float4 v1 = ((const float4*)src)[o * 2 + 1];
            __half h[8] = {__float2half(v0.x), __float2half(v0.y),
                           __float2half(v0.z), __float2half(v0.w),
                           __float2half(v1.x), __float2half(v1.y),
                           __float2half(v1.z), __float2half(v1.w)};
            ((uint4*)dst)[o] = *(uint4*)h;
        }
        return;
    }

    // ---- router ----
    extern __shared__ float sm[];
    float* wg_s   = sm;                       // [16][1024]
    float* x_s    = sm + NEXP * DMODEL;       // [1024]
    float* logits = sm + NEXP * DMODEL + DMODEL;

    for (int i = tid; i < NEXP * DMODEL / 4; i += 256)
        ((float4*)wg_s)[i] = ((const float4*)Wg)[i];
    __syncthreads();

    int e = tid >> 4, l = tid & 15;
    const float* wr = wg_s + e * DMODEL;

    for (int t = 0; t < TOK_PER_BLK; t++) {
        int n = blockIdx.x * TOK_PER_BLK + t;
        // stage x row
        ((float4*)x_s)[tid] = ((const float4*)(x + (size_t)n * DMODEL))[tid];
        __syncthreads();
        // 16 logits, 16 lanes each
        float s = 0.f;
#pragma unroll 8
        for (int d = l; d < DMODEL; d += 16) s += x_s[d] * wr[d];
        s += __shfl_down_sync(0xffffffffu, s, 8, 16);
        s += __shfl_down_sync(0xffffffffu, s, 4, 16);
        s += __shfl_down_sync(0xffffffffu, s, 2, 16);
        s += __shfl_down_sync(0xffffffffu, s, 1, 16);
        if (l == 0) logits[e] = s;
        __syncthreads();
        // convert x row to fp16 (all threads) while thread 0 does top-2
        {
            float4 v = ((float4*)x_s)[tid];
            __half h[4] = {__float2half(v.x), __float2half(v.y),
                           __float2half(v.z), __float2half(v.w)};
            ((uint2*)(g_x + (size_t)n * DMODEL))[tid] = *(uint2*)h;
        }
        if (tid == 0) {
            int i1 = 0; float v1 = logits[0];
#pragma unroll
            for (int j = 1; j < NEXP; j++) if (logits[j] > v1) { v1 = logits[j]; i1 = j; }
            int i2 = -1; float v2 = -3.4e38f;
#pragma unroll
            for (int j = 0; j < NEXP; j++) if (j != i1 && logits[j] > v2) { v2 = logits[j]; i2 = j; }
            float w1 = 1.f / (1.f + expf(v2 - v1));
            float w2 = 1.f - w1;
            int p1 = atomicAdd(&g_cnt[i1], 1);
            g_slot[i1][p1] = n * 2;     g_gate[i1][p1] = w1;
            int p2 = atomicAdd(&g_cnt[i2], 1);
            g_slot[i2][p2] = n * 2 + 1; g_gate[i2][p2] = w2;
        }
        __syncthreads();
    }
}

// ---------------- GEMM1: H = silu(X W1) * (X W3) -----------------------------
// CTA 128m x 64n, 256 threads (8 warps 4m x 2n), warp 32m x 32n dual-acc.
// k-chunk 64, 3-stage single-sync pipeline.
// blockIdx.y == DINTER/64 (11): converter CTAs streaming W2 fp32->fp16 (overlap).
// Stage: A 16KB (SW128) | B 2 mats x 64 k-rows x 144B (padded) = 34816B
#define G1_BROW  144
#define G1_STAGE (16384 + 2*64*G1_BROW)
#define G1_SMEM  (1024 + 3*G1_STAGE)
#define NCVT     512   // converter CTAs (32 x-tiles * 16 experts at y==11)

__global__ __launch_bounds__(256, 2) void k_gemm1(const float* __restrict__ W2) {
    // ---- converter slice: overlap W2 conversion with the GEMM CTAs ----
    if (blockIdx.y == DINTER / 64) {
        size_t cid = (size_t)blockIdx.z * 32 + blockIdx.x;      // 0..511
        for (size_t off = cid * 256 + threadIdx.x; off < WGRP; off += (size_t)NCVT * 256) {
            float4 v0 = ((const float4*)W2)[off * 2];
            float4 v1 = ((const float4*)W2)[off * 2 + 1];
            __half h[8] = {__float2half(v0.x), __float2half(v0.y),
                           __float2half(v0.z), __float2half(v0.w),
                           __float2half(v1.x), __float2half(v1.y),
                           __float2half(v1.z), __float2half(v1.w)};
            ((uint4*)g_w2)[off] = *(uint4*)h;
        }
        return;
    }

    int e = blockIdx.z;
    int cnt = g_cnt[e];
    int m0 = blockIdx.x * 128;
    if (m0 >= cnt) return;
    int n0 = blockIdx.y * 64;

    extern __shared__ char smem[];
    int* rows = (int*)smem;
    uint32_t sb = s2u(smem);
    int tid = threadIdx.x, lane = tid & 31, wid = tid >> 5;

    if (tid < 128) {
        int m = m0 + tid;
        rows[tid] = g_slot[e][m < cnt ? m : cnt - 1];
    }
    __syncthreads();

    const __half* w1 = g_w1 + (size_t)e * DMODEL * DINTER;
    const __half* w3 = g_w3 + (size_t)e * DMODEL * DINTER;

    auto load_stage = [&](int it) {
        uint32_t base = sb + 1024 + (it % 3) * G1_STAGE;
        int k0 = it * 64;
#pragma unroll
        for (int q = 0; q < 4; q++) {          // A: 128 rows x 8 chunks, SW128
            int i = tid + q * 256;
            int r = i >> 3, c = i & 7;
            const __half* src = g_x + (size_t)(rows[r] >> 1) * DMODEL + k0 + c * 8;
            cp16(base + SWZ(r * 128 + c * 16), src);
        }
#pragma unroll
        for (int q = 0; q < 4; q++) {          // B: 2 mats x 64 k-rows x 8 chunks, [k][n]
            int i = tid + q * 256;
            int c = i & 7;
            int r = (i >> 3) & 63;
            int mat = i >> 9;
            const __half* src = (mat ? w3 : w1) + (size_t)(k0 + r) * DINTER + n0 + c * 8;
            cp16(base + 16384 + mat * (64 * G1_BROW) + r * G1_BROW + c * 16, src);
        }
        CP_COMMIT();
    };

    float acc1[2][4][4] = {}, acc3[2][4][4] = {};
    int m0w = (wid & 3) * 32, n0w = (wid >> 2) * 32;

    load_stage(0);
    load_stage(1);
    const int ITERS = DMODEL / 64;   // 16
    for (int it = 0; it < ITERS; ++it) {
        if (it + 1 < ITERS) CP_WAIT1(); else CP_WAIT0();
        __syncthreads();
        if (it + 2 < ITERS) load_stage(it + 2);
        uint32_t a = sb + 1024 + (it % 3) * G1_STAGE;
        uint32_t b = a + 16384;
#pragma unroll
        for (int ks = 0; ks < 4; ++ks) {
            uint32_t ah[2][4];
            int colh = ks * 32 + ((lane >> 4) << 4);
#pragma unroll
            for (int i = 0; i < 2; i++) {
                int row = m0w + i * 16 + (lane & 15);
                ldsm4(ah[i][0], ah[i][1], ah[i][2], ah[i][3], a + SWZ(row * 128 + colh));
            }
            // trans B: lane -> k-row, n-col base
            int kl = ks * 16 + ((lane >> 3) & 1) * 8 + (lane & 7);
            int nb = (lane >> 4) * 8;
#pragma unroll
            for (int jj = 0; jj < 2; jj++) {
                int nc = n0w + jj * 16 + nb;
                uint32_t b1[4], b3[4];
                ldsm4t(b1[0], b1[1], b1[2], b1[3], b + kl * G1_BROW + nc * 2);
                ldsm4t(b3[0], b3[1], b3[2], b3[3], b + 64 * G1_BROW + kl * G1_BROW + nc * 2);
#pragma unroll
                for (int i = 0; i < 2; i++) {
                    mma16816(acc1[i][jj * 2 + 0], ah[i], b1 + 0);
                    mma16816(acc1[i][jj * 2 + 1], ah[i], b1 + 2);
                    mma16816(acc3[i][jj * 2 + 0], ah[i], b3 + 0);
                    mma16816(acc3[i][jj * 2 + 1], ah[i], b3 + 2);
                }
            }
        }
    }

    // epilogue: silu(acc1)*acc3, fp16, store H
    int gr = lane >> 2, gc = (lane & 3) * 2;
#pragma unroll
    for (int i = 0; i < 2; i++) {
#pragma unroll
        for (int half = 0; half < 2; half++) {
            int m = m0w + i * 16 + gr + half * 8;
            if (m0 + m < cnt) {
                int slot = rows[m];
                __half* ph = g_h + (size_t)slot * DINTER + n0 + n0w;
#pragma unroll
                for (int j = 0; j < 4; j++) {
                    float a0 = acc1[i][j][half * 2 + 0], a1 = acc1[i][j][half * 2 + 1];
                    float c0 = acc3[i][j][half * 2 + 0], c1 = acc3[i][j][half * 2 + 1];
                    float s0 = a0 / (1.f + __expf(-a0)) * c0;
                    float s1 = a1 / (1.f + __expf(-a1)) * c1;
                    union { __half b[2]; uint32_t u; } uh;
                    uh.b[0] = __float2half(s0);
                    uh.b[1] = __float2half(s1);
                    *(uint32_t*)(ph + j * 8 + gc) = uh.u;
                }
            }
        }
    }
}

// ---------------- GEMM2: out += gate * (H W2) --------------------------------
// CTA 128m x 128n, 256 threads, k-chunk 64, 11 iters, 3-stage. warp = 32m x 64n.
// Stage: A 16KB | B 64 k-rows x 272B (padded) = 33792B
#define G2_BROW  272
#define G2_STAGE (16384 + 64*G2_BROW)
#define G2_SMEM  (1024 + 3*G2_STAGE)

__global__ __launch_bounds__(256, 2) void k_gemm2(float* __restrict__ out) {
    int e = blockIdx.z;
    int cnt = g_cnt[e];
    int m0 = blockIdx.x * 128;
    if (m0 >= cnt) return;
    int n0 = blockIdx.y * 128;

    extern __shared__ char smem[];
    int*   rows  = (int*)smem;
    float* gates = (float*)(smem + 512);
    uint32_t sb = s2u(smem);
    int tid = threadIdx.x, lane = tid & 31, wid = tid >> 5;

    if (tid < 128) {
        int m = m0 + tid;
        int mm = m < cnt ? m : cnt - 1;
        rows[tid]  = g_slot[e][mm];
        gates[tid] = g_gate[e][mm];
    }
    __syncthreads();

    const __half* w2 = g_w2 + (size_t)e * DINTER * DMODEL;

    auto load_stage = [&](int it) {
        uint32_t base = sb + 1024 + (it % 3) * G2_STAGE;
        int k0 = it * 64;
#pragma unroll
        for (int q = 0; q < 4; q++) {          // A: 128 gathered H rows, SW128
            int i = tid + q * 256;
            int r = i >> 3, c = i & 7;
            const __half* src = g_h + (size_t)rows[r] * DINTER + k0 + c * 8;
            cp16(base + SWZ(r * 128 + c * 16), src);
        }
#pragma unroll
        for (int q = 0; q < 4; q++) {          // B: 64 k-rows x 16 chunks (128 n), [k][n]
            int i = tid + q * 256;
            int c = i & 15;
            int r = i >> 4;
            const __half* src = w2 + (size_t)(k0 + r) * DMODEL + n0 + c * 8;
            cp16(base + 16384 + r * G2_BROW + c * 16, src);
        }
        CP_COMMIT();
    };

    float acc[2][8][4] = {};
    int m0w = (wid & 3) * 32, n0w = (wid >> 2) * 64;

    load_stage(0);
    load_stage(1);
    const int ITERS = DINTER / 64;   // 11
    for (int it = 0; it < ITERS; ++it) {
        if (it + 1 < ITERS) CP_WAIT1(); else CP_WAIT0();
        __syncthreads();
        if (it + 2 < ITERS) load_stage(it + 2);
        uint32_t a = sb + 1024 + (it % 3) * G2_STAGE;
        uint32_t b = a + 16384;
#pragma unroll
        for (int ks = 0; ks < 4; ++ks) {
            uint32_t ah[2][4];
            int colh = ks * 32 + ((lane >> 4) << 4);
#pragma unroll
            for (int i = 0; i < 2; i++) {
                int row = m0w + i * 16 + (lane & 15);
                ldsm4(ah[i][0], ah[i][1], ah[i][2], ah[i][3], a + SWZ(row * 128 + colh));
            }
            int kl = ks * 16 + ((lane >> 3) & 1) * 8 + (lane & 7);
            int nb = (lane >> 4) * 8;
#pragma unroll
            for (int jj = 0; jj < 4; jj++) {
                int nc = n0w + jj * 16 + nb;
                uint32_t bw[4];
                ldsm4t(bw[0], bw[1], bw[2], bw[3], b + kl * G2_BROW + nc * 2);
#pragma unroll
                for (int i = 0; i < 2; i++) {
                    mma16816(acc[i][jj * 2 + 0], ah[i], bw + 0);
                    mma16816(acc[i][jj * 2 + 1], ah[i], bw + 2);
                }
            }
        }
    }

    int gr = lane >> 2, gc = (lane & 3) * 2;
#pragma unroll
    for (int i = 0; i < 2; i++) {
#pragma unroll
        for (int half = 0; half < 2; half++) {
            int m = m0w + i * 16 + gr + half * 8;
            if (m0 + m < cnt) {
                int tok = rows[m] >> 1;
                float g = gates[m];
                float* op = out + (size_t)tok * DMODEL + n0 + n0w;
#pragma unroll
                for (int j = 0; j < 8; j++) {
                    atomicAdd(op + j * 8 + gc + 0, g * acc[i][j][half * 2 + 0]);
                    atomicAdd(op + j * 8 + gc + 1, g * acc[i][j][half * 2 + 1]);
                }
            }
        }
    }
}

// ---------------------------------------------------------------------------
extern "C" void kernel_launch(void* const* d_in, const int* in_sizes, int n_in,
                              void* d_out, int out_size) {
    const float* x  = (const float*)d_in[0];
    const float* Wg = (const float*)d_in[1];
    const float* W1 = (const float*)d_in[2];
    const float* W2 = (const float*)d_in[3];
    const float* W3 = (const float*)d_in[4];
    float* out = (float*)d_out;

    cudaFuncSetAttribute(k_prep,  cudaFuncAttributeMaxDynamicSharedMemorySize, PREP_SMEM);
    cudaFuncSetAttribute(k_gemm1, cudaFuncAttributeMaxDynamicSharedMemorySize, G1_SMEM);
    cudaFuncSetAttribute(k_gemm2, cudaFuncAttributeMaxDynamicSharedMemorySize, G2_SMEM);

    cudaMemsetAsync(d_out, 0, (size_t)out_size * sizeof(float), 0);
    k_reset<<<1, 32>>>();
    // fused: router (256 blocks) + W1/W3 conversion (768 blocks) + x conversion
    k_prep<<<PREP_RTR + PREP_CVT, 256, PREP_SMEM>>>(x, Wg, W1, W3);

    // grid.y = 12: y 0..10 = GEMM n-tiles, y 11 = W2-converter CTAs (overlap)
    k_gemm1<<<dim3(NTOK / 128, DINTER / 64 + 1, NEXP), 256, G1_SMEM>>>(W2);
    k_gemm2<<<dim3(NTOK / 128, DMODEL / 128, NEXP), 256, G2_SMEM>>>(out);
}

// round 17
// speedup vs baseline: 1.0498x; 1.0014x over previous
#include <cuda_runtime.h>
#include <cuda_fp16.h>
#include <math.h>
#include <stdint.h>

#define NTOK   4096
#define DMODEL 1024
#define DINTER 704
#define NEXP   16
#define NSLOT  (NTOK*2)

// ---------------- device scratch (no allocations allowed) -------------------
__device__ int   g_cnt[NEXP];
__device__ int   g_slot[NEXP][NTOK];
__device__ float g_gate[NEXP][NTOK];

__device__ __align__(16) __half g_x[(size_t)NTOK*DMODEL];
// weights in NATIVE [k][n] layout, fp16: W1/W3 [e][1024][704], W2 [e][704][1024]
__device__ __align__(16) __half g_w1[(size_t)NEXP*DMODEL*DINTER];
__device__ __align__(16) __half g_w3[(size_t)NEXP*DMODEL*DINTER];
__device__ __align__(16) __half g_w2[(size_t)NEXP*DINTER*DMODEL];
__device__ __align__(16) __half g_h[(size_t)NSLOT*DINTER];

// ---------------- PTX helpers ----------------------------------------------
__device__ __forceinline__ uint32_t s2u(const void* p) {
    uint32_t a;
    asm("{ .reg .u64 t; cvta.to.shared.u64 t, %1; cvt.u32.u64 %0, t; }" : "=r"(a) : "l"(p));
    return a;
}
#define SWZ(o) ((o) ^ (((o) >> 3) & 0x70))

__device__ __forceinline__ void cp16(uint32_t dst, const void* src) {
    asm volatile("cp.async.cg.shared.global [%0], [%1], 16;" :: "r"(dst), "l"(src));
}
#define CP_COMMIT() asm volatile("cp.async.commit_group;" ::: "memory")
#define CP_WAIT1()  asm volatile("cp.async.wait_group 1;" ::: "memory")
#define CP_WAIT0()  asm volatile("cp.async.wait_group 0;" ::: "memory")

__device__ __forceinline__ void ldsm4(uint32_t& r0, uint32_t& r1, uint32_t& r2, uint32_t& r3,
                                      uint32_t addr) {
    asm volatile("ldmatrix.sync.aligned.m8n8.x4.shared.b16 {%0,%1,%2,%3}, [%4];"
                 : "=r"(r0), "=r"(r1), "=r"(r2), "=r"(r3) : "r"(addr));
}
__device__ __forceinline__ void ldsm4t(uint32_t& r0, uint32_t& r1, uint32_t& r2, uint32_t& r3,
                                       uint32_t addr) {
    asm volatile("ldmatrix.sync.aligned.m8n8.x4.trans.shared.b16 {%0,%1,%2,%3}, [%4];"
                 : "=r"(r0), "=r"(r1), "=r"(r2), "=r"(r3) : "r"(addr));
}
__device__ __forceinline__ void mma16816(float* d, const uint32_t* a, const uint32_t* b) {
    asm volatile(
        "mma.sync.aligned.m16n8k16.row.col.f32.f16.f16.f32 "
        "{%0,%1,%2,%3},{%4,%5,%6,%7},{%8,%9},{%0,%1,%2,%3};"
        : "+f"(d[0]), "+f"(d[1]), "+f"(d[2]), "+f"(d[3])
        : "r"(a[0]), "r"(a[1]), "r"(a[2]), "r"(a[3]), "r"(b[0]), "r"(b[1]));
}

// ---------------- small kernels ----------------------------------------------
__global__ void k_reset() {
    if (threadIdx.x < NEXP) g_cnt[threadIdx.x] = 0;
}

// ---------------- fused prep: router + x->fp16 + W1/W3->fp16 ------------------
// blocks [0, 256): router, 16 tokens each, Wg cached in smem, x row staged+converted
// blocks [256, 1024): grid-stride streaming conversion of W1 | W3
#define WGRP ((size_t)NEXP*DMODEL*DINTER/8)   // 1441792 uint4-groups per weight
#define PREP_RTR   256
#define PREP_CVT   768
#define TOK_PER_BLK 16
#define PREP_SMEM  (DMODEL*NEXP*4 + DMODEL*4 + 64)   // Wg 64KB + xrow 4KB + logits

__global__ __launch_bounds__(256) void k_prep(const float* __restrict__ x,
                                              const float* __restrict__ Wg,
                                              const float* __restrict__ W1,
                                              const float* __restrict__ W3) {
    int tid = threadIdx.x;
    if (blockIdx.x >= PREP_RTR) {
        // ---- converter: W1 | W3 fp32 -> fp16, streaming ----
        size_t cid = blockIdx.x - PREP_RTR;
        for (size_t off = cid * 256 + tid; off < 2 * WGRP; off += (size_t)PREP_CVT * 256) {
            const float* src; __half* dst; size_t o;
            if (off < WGRP) { src = W1; dst = g_w1; o = off; }
            else            { src = W3; dst = g_w3; o = off - WGRP; }
            float4 v0 = ((const float4*)src)[o * 2];
            float4 v1 = ((const float4*)src)[o * 2 + 1];
            __half h[8] = {__float2half(v0.x), __float2half(v0.y),
                           __float2half(v0.z), __float2half(v0.w),
                           __float2half(v1.x), __float2half(v1.y),
                           __float2half(v1.z), __float2half(v1.w)};
            ((uint4*)dst)[o] = *(uint4*)h;
        }
        return;
    }

    // ---- router ----
    extern __shared__ float sm[];
    float* wg_s   = sm;                       // [16][1024]
    float* x_s    = sm + NEXP * DMODEL;       // [1024]
    float* logits = sm + NEXP * DMODEL + DMODEL;

    for (int i = tid; i < NEXP * DMODEL / 4; i += 256)
        ((float4*)wg_s)[i] = ((const float4*)Wg)[i];
    __syncthreads();

    int e = tid >> 4, l = tid & 15;
    const float* wr = wg_s + e * DMODEL;

    for (int t = 0; t < TOK_PER_BLK; t++) {
        int n = blockIdx.x * TOK_PER_BLK + t;
        // stage x row
        ((float4*)x_s)[tid] = ((const float4*)(x + (size_t)n * DMODEL))[tid];
        __syncthreads();
        // 16 logits, 16 lanes each
        float s = 0.f;
#pragma unroll 8
        for (int d = l; d < DMODEL; d += 16) s += x_s[d] * wr[d];
        s += __shfl_down_sync(0xffffffffu, s, 8, 16);
        s += __shfl_down_sync(0xffffffffu, s, 4, 16);
        s += __shfl_down_sync(0xffffffffu, s, 2, 16);
        s += __shfl_down_sync(0xffffffffu, s, 1, 16);
        if (l == 0) logits[e] = s;
        __syncthreads();
        // convert x row to fp16 (all threads) while thread 0 does top-2
        {
            float4 v = ((float4*)x_s)[tid];
            __half h[4] = {__float2half(v.x), __float2half(v.y),
                           __float2half(v.z), __float2half(v.w)};
            ((uint2*)(g_x + (size_t)n * DMODEL))[tid] = *(uint2*)h;
        }
        if (tid == 0) {
            int i1 = 0; float v1 = logits[0];
#pragma unroll
            for (int j = 1; j < NEXP; j++) if (logits[j] > v1) { v1 = logits[j]; i1 = j; }
            int i2 = -1; float v2 = -3.4e38f;
#pragma unroll
            for (int j = 0; j < NEXP; j++) if (j != i1 && logits[j] > v2) { v2 = logits[j]; i2 = j; }
            float w1 = 1.f / (1.f + expf(v2 - v1));
            float w2 = 1.f - w1;
            int p1 = atomicAdd(&g_cnt[i1], 1);
            g_slot[i1][p1] = n * 2;     g_gate[i1][p1] = w1;
            int p2 = atomicAdd(&g_cnt[i2], 1);
            g_slot[i2][p2] = n * 2 + 1; g_gate[i2][p2] = w2;
        }
        __syncthreads();
    }
}

// ---------------- GEMM1: H = silu(X W1) * (X W3) -----------------------------
// CTA 128m x 64n, 256 threads (8 warps 4m x 2n), warp 32m x 32n dual-acc.
// k-chunk 64, 3-stage single-sync pipeline.
// blockIdx.y == DINTER/64 (11): converter CTAs streaming W2 fp32->fp16 (overlap).
// Stage: A 16KB (SW128) | B 2 mats x 64 k-rows x 144B (padded) = 34816B
#define G1_BROW  144
#define G1_STAGE (16384 + 2*64*G1_BROW)
#define G1_SMEM  (1024 + 3*G1_STAGE)
#define NCVT     512   // converter CTAs (32 x-tiles * 16 experts at y==11)

__global__ __launch_bounds__(256, 2) void k_gemm1(const float* __restrict__ W2) {
    // ---- converter slice: overlap W2 conversion with the GEMM CTAs ----
    if (blockIdx.y == DINTER / 64) {
        size_t cid = (size_t)blockIdx.z * 32 + blockIdx.x;      // 0..511
        for (size_t off = cid * 256 + threadIdx.x; off < WGRP; off += (size_t)NCVT * 256) {
            float4 v0 = ((const float4*)W2)[off * 2];
            float4 v1 = ((const float4*)W2)[off * 2 + 1];
            __half h[8] = {__float2half(v0.x), __float2half(v0.y),
                           __float2half(v0.z), __float2half(v0.w),
                           __float2half(v1.x), __float2half(v1.y),
                           __float2half(v1.z), __float2half(v1.w)};
            ((uint4*)g_w2)[off] = *(uint4*)h;
        }
        return;
    }

    int e = blockIdx.z;
    int cnt = g_cnt[e];
    int m0 = blockIdx.x * 128;
    if (m0 >= cnt) return;
    int n0 = blockIdx.y * 64;

    extern __shared__ char smem[];
    int* rows = (int*)smem;
    uint32_t sb = s2u(smem);
    int tid = threadIdx.x, lane = tid & 31, wid = tid >> 5;

    if (tid < 128) {
        int m = m0 + tid;
        rows[tid] = g_slot[e][m < cnt ? m : cnt - 1];
    }
    __syncthreads();

    const __half* w1 = g_w1 + (size_t)e * DMODEL * DINTER;
    const __half* w3 = g_w3 + (size_t)e * DMODEL * DINTER;

    auto load_stage = [&](int it) {
        uint32_t base = sb + 1024 + (it % 3) * G1_STAGE;
        int k0 = it * 64;
#pragma unroll
        for (int q = 0; q < 4; q++) {          // A: 128 rows x 8 chunks, SW128
            int i = tid + q * 256;
            int r = i >> 3, c = i & 7;
            const __half* src = g_x + (size_t)(rows[r] >> 1) * DMODEL + k0 + c * 8;
            cp16(base + SWZ(r * 128 + c * 16), src);
        }
#pragma unroll
        for (int q = 0; q < 4; q++) {          // B: 2 mats x 64 k-rows x 8 chunks, [k][n]
            int i = tid + q * 256;
            int c = i & 7;
            int r = (i >> 3) & 63;
            int mat = i >> 9;
            const __half* src = (mat ? w3 : w1) + (size_t)(k0 + r) * DINTER + n0 + c * 8;
            cp16(base + 16384 + mat * (64 * G1_BROW) + r * G1_BROW + c * 16, src);
        }
        CP_COMMIT();
    };

    float acc1[2][4][4] = {}, acc3[2][4][4] = {};
    int m0w = (wid & 3) * 32, n0w = (wid >> 2) * 32;

    load_stage(0);
    load_stage(1);
    const int ITERS = DMODEL / 64;   // 16
    for (int it = 0; it < ITERS; ++it) {
        if (it + 1 < ITERS) CP_WAIT1(); else CP_WAIT0();
        __syncthreads();
        if (it + 2 < ITERS) load_stage(it + 2);
        uint32_t a = sb + 1024 + (it % 3) * G1_STAGE;
        uint32_t b = a + 16384;
#pragma unroll
        for (int ks = 0; ks < 4; ++ks) {
            uint32_t ah[2][4];
            int colh = ks * 32 + ((lane >> 4) << 4);
#pragma unroll
            for (int i = 0; i < 2; i++) {
                int row = m0w + i * 16 + (lane & 15);
                ldsm4(ah[i][0], ah[i][1], ah[i][2], ah[i][3], a + SWZ(row * 128 + colh));
            }
            // trans B: lane -> k-row, n-col base
            int kl = ks * 16 + ((lane >> 3) & 1) * 8 + (lane & 7);
            int nb = (lane >> 4) * 8;
#pragma unroll
            for (int jj = 0; jj < 2; jj++) {
                int nc = n0w + jj * 16 + nb;
                uint32_t b1[4], b3[4];
                ldsm4t(b1[0], b1[1], b1[2], b1[3], b + kl * G1_BROW + nc * 2);
                ldsm4t(b3[0], b3[1], b3[2], b3[3], b + 64 * G1_BROW + kl * G1_BROW + nc * 2);
#pragma unroll
                for (int i = 0; i < 2; i++) {
                    mma16816(acc1[i][jj * 2 + 0], ah[i], b1 + 0);
                    mma16816(acc1[i][jj * 2 + 1], ah[i], b1 + 2);
                    mma16816(acc3[i][jj * 2 + 0], ah[i], b3 + 0);
                    mma16816(acc3[i][jj * 2 + 1], ah[i], b3 + 2);
                }
            }
        }
    }

    // epilogue: silu(acc1)*acc3, fp16, store H
    int gr = lane >> 2, gc = (lane & 3) * 2;
#pragma unroll
    for (int i = 0; i < 2; i++) {
#pragma unroll
        for (int half = 0; half < 2; half++) {
            int m = m0w + i * 16 + gr + half * 8;
            if (m0 + m < cnt) {
                int slot = rows[m];
                __half* ph = g_h + (size_t)slot * DINTER + n0 + n0w;
#pragma unroll
                for (int j = 0; j < 4; j++) {
                    float a0 = acc1[i][j][half * 2 + 0], a1 = acc1[i][j][half * 2 + 1];
                    float c0 = acc3[i][j][half * 2 + 0], c1 = acc3[i][j][half * 2 + 1];
                    float s0 = a0 / (1.f + __expf(-a0)) * c0;
                    float s1 = a1 / (1.f + __expf(-a1)) * c1;
                    union { __half b[2]; uint32_t u; } uh;
                    uh.b[0] = __float2half(s0);
                    uh.b[1] = __float2half(s1);
                    *(uint32_t*)(ph + j * 8 + gc) = uh.u;
                }
            }
        }
    }
}

// ---------------- GEMM2: out += gate * (H W2) --------------------------------
// CTA 128m x 128n, 256 threads, k-chunk 64, 11 iters, 3-stage. warp = 32m x 64n.
// Stage: A 16KB | B 64 k-rows x 272B (padded) = 33792B
#define G2_BROW  272
#define G2_STAGE (16384 + 64*G2_BROW)
#define G2_SMEM  (1024 + 3*G2_STAGE)

__global__ __launch_bounds__(256, 2) void k_gemm2(float* __restrict__ out) {
    int e = blockIdx.z;
    int cnt = g_cnt[e];
    int m0 = blockIdx.x * 128;
    if (m0 >= cnt) return;
    int n0 = blockIdx.y * 128;

    extern __shared__ char smem[];
    int*   rows  = (int*)smem;
    float* gates = (float*)(smem + 512);
    uint32_t sb = s2u(smem);
    int tid = threadIdx.x, lane = tid & 31, wid = tid >> 5;

    if (tid < 128) {
        int m = m0 + tid;
        int mm = m < cnt ? m : cnt - 1;
        rows[tid]  = g_slot[e][mm];
        gates[tid] = g_gate[e][mm];
    }
    __syncthreads();

    const __half* w2 = g_w2 + (size_t)e * DINTER * DMODEL;

    auto load_stage = [&](int it) {
        uint32_t base = sb + 1024 + (it % 3) * G2_STAGE;
        int k0 = it * 64;
#pragma unroll
        for (int q = 0; q < 4; q++) {          // A: 128 gathered H rows, SW128
            int i = tid + q * 256;
            int r = i >> 3, c = i & 7;
            const __half* src = g_h + (size_t)rows[r] * DINTER + k0 + c * 8;
            cp16(base + SWZ(r * 128 + c * 16), src);
        }
#pragma unroll
        for (int q = 0; q < 4; q++) {          // B: 64 k-rows x 16 chunks (128 n), [k][n]
            int i = tid + q * 256;
            int c = i & 15;
            int r = i >> 4;
            const __half* src = w2 + (size_t)(k0 + r) * DMODEL + n0 + c * 8;
            cp16(base + 16384 + r * G2_BROW + c * 16, src);
        }
        CP_COMMIT();
    };

    float acc[2][8][4] = {};
    int m0w = (wid & 3) * 32, n0w = (wid >> 2) * 64;

    load_stage(0);
    load_stage(1);
    const int ITERS = DINTER / 64;   // 11
    for (int it = 0; it < ITERS; ++it) {
        if (it + 1 < ITERS) CP_WAIT1(); else CP_WAIT0();
        __syncthreads();
        if (it + 2 < ITERS) load_stage(it + 2);
        uint32_t a = sb + 1024 + (it % 3) * G2_STAGE;
        uint32_t b = a + 16384;
#pragma unroll
        for (int ks = 0; ks < 4; ++ks) {
            uint32_t ah[2][4];
            int colh = ks * 32 + ((lane >> 4) << 4);
#pragma unroll
            for (int i = 0; i < 2; i++) {
                int row = m0w + i * 16 + (lane & 15);
                ldsm4(ah[i][0], ah[i][1], ah[i][2], ah[i][3], a + SWZ(row * 128 + colh));
            }
            int kl = ks * 16 + ((lane >> 3) & 1) * 8 + (lane & 7);
            int nb = (lane >> 4) * 8;
#pragma unroll
            for (int jj = 0; jj < 4; jj++) {
                int nc = n0w + jj * 16 + nb;
                uint32_t bw[4];
                ldsm4t(bw[0], bw[1], bw[2], bw[3], b + kl * G2_BROW + nc * 2);
#pragma unroll
                for (int i = 0; i < 2; i++) {
                    mma16816(acc[i][jj * 2 + 0], ah[i], bw + 0);
                    mma16816(acc[i][jj * 2 + 1], ah[i], bw + 2);
                }
            }
        }
    }

    int gr = lane >> 2, gc = (lane & 3) * 2;
#pragma unroll
    for (int i = 0; i < 2; i++) {
#pragma unroll
        for (int half = 0; half < 2; half++) {
            int m = m0w + i * 16 + gr + half * 8;
            if (m0 + m < cnt) {
                int tok = rows[m] >> 1;
                float g = gates[m];
                float* op = out + (size_t)tok * DMODEL + n0 + n0w;
#pragma unroll
                for (int j = 0; j < 8; j++) {
                    atomicAdd(op + j * 8 + gc + 0, g * acc[i][j][half * 2 + 0]);
                    atomicAdd(op + j * 8 + gc + 1, g * acc[i][j][half * 2 + 1]);
                }
            }
        }
    }
}

// ---------------------------------------------------------------------------
extern "C" void kernel_launch(void* const* d_in, const int* in_sizes, int n_in,
                              void* d_out, int out_size) {
    const float* x  = (const float*)d_in[0];
    const float* Wg = (const float*)d_in[1];
    const float* W1 = (const float*)d_in[2];
    const float* W2 = (const float*)d_in[3];
    const float* W3 = (const float*)d_in[4];
    float* out = (float*)d_out;

    cudaFuncSetAttribute(k_prep,  cudaFuncAttributeMaxDynamicSharedMemorySize, PREP_SMEM);
    cudaFuncSetAttribute(k_gemm1, cudaFuncAttributeMaxDynamicSharedMemorySize, G1_SMEM);
    cudaFuncSetAttribute(k_gemm2, cudaFuncAttributeMaxDynamicSharedMemorySize, G2_SMEM);

    cudaMemsetAsync(d_out, 0, (size_t)out_size * sizeof(float), 0);
    k_reset<<<1, 32>>>();
    // fused: router (256 blocks) + W1/W3 conversion (768 blocks) + x conversion
    k_prep<<<PREP_RTR + PREP_CVT, 256, PREP_SMEM>>>(x, Wg, W1, W3);

    // grid.y = 12: y 0..10 = GEMM n-tiles, y 11 = W2-converter CTAs (overlap)
    k_gemm1<<<dim3(NTOK / 128, DINTER / 64 + 1, NEXP), 256, G1_SMEM>>>(W2);
    k_gemm2<<<dim3(NTOK / 128, DMODEL / 128, NEXP), 256, G2_SMEM>>>(out);
}